// round 14
// baseline (speedup 1.0000x reference)
#include <cuda_runtime.h>
#include <cuda_fp16.h>

#define N_NODES 50000
#define N_EDGES 800000
#define NEG_SLOPE 0.2f
#define SCAN_B 196          // ceil(50000/256)
#define GEMM_B 391          // ceil(50000/128)
#define HIST_B 196

// ---------------- scratch (device globals) ---------------------------------
__device__ __align__(16) __half g_xh16[(size_t)N_NODES * 128]; // x @ W in fp16
__device__ __align__(16) float g_si[N_NODES * 4];
__device__ __align__(16) float g_sj[N_NODES * 4];
__device__ float g_sew[32];                                 // folded We * a_e  [c][h]
__device__ int   g_cur[N_NODES];                            // counts -> cursors
__device__ int   g_off[N_NODES + 1];                        // CSR offsets by dst
__device__ unsigned long long g_state[SCAN_B];              // lookback scan state
__device__ __align__(16) int4 g_rec[N_EDGES];               // {src, a01f16, a23f16, pad}

// ---------------- f32x2 packed-FMA helpers (Blackwell FFMA2) ----------------
__device__ __forceinline__ void ffma2(unsigned long long& d,
                                      unsigned long long a,
                                      unsigned long long b) {
    asm("fma.rn.f32x2 %0, %1, %2, %0;" : "+l"(d) : "l"(a), "l"(b));
}
__device__ __forceinline__ unsigned long long bcast2(float x) {
    unsigned long long r;
    unsigned int u = __float_as_uint(x);
    asm("mov.b64 %0, {%1, %1};" : "=l"(r) : "r"(u));
    return r;
}
__device__ __forceinline__ float2 unpack2(unsigned long long v) {
    unsigned int a, b;
    asm("mov.b64 {%0, %1}, %2;" : "=r"(a), "=r"(b) : "l"(v));
    return make_float2(__uint_as_float(a), __uint_as_float(b));
}

// ---------------- K0: init counts, scan state, fold We*a_e ------------------
__global__ void k_init(const float* __restrict__ We, const float* __restrict__ att) {
    int i = blockIdx.x * blockDim.x + threadIdx.x;
    if (i < N_NODES) g_cur[i] = 0;
    if (i < SCAN_B) g_state[i] = 0ULL;
    if (i == 0) g_off[N_NODES] = N_EDGES;
    if (i < 32) {
        int h = i & 3, c = i >> 2;
        float s = 0.0f;
        #pragma unroll
        for (int p = 0; p < 4; p++)
            s += __ldg(We + c * 16 + h * 4 + p) * __ldg(att + h * 68 + 64 + p);
        g_sew[c * 4 + h] = s;
    }
}

// ---------------- K1: heterogeneous grid: GEMM tiles + dst histogram --------
#define KP 32
#define XSTR 132
__global__ __launch_bounds__(256, 2) void k_gemm_hist(const float* __restrict__ x,
                                                      const float* __restrict__ W,
                                                      const float* __restrict__ att,
                                                      const int* __restrict__ ei) {
    __shared__ __align__(16) float sW[KP][128];
    __shared__ __align__(16) float sX[KP][XSTR];
    __shared__ float sSi[8][32][4];
    __shared__ float sSj[8][32][4];
    int t = threadIdx.x;

    if (blockIdx.x >= GEMM_B) {
        int base = (blockIdx.x - GEMM_B) * 256 + t;
        const int stride = HIST_B * 256;
        #pragma unroll 4
        for (int e = base; e < N_EDGES; e += stride)
            atomicAdd(&g_cur[__ldg(ei + N_EDGES + e)], 1);
        return;
    }

    int lane = t & 31;
    int warp = t >> 5;
    int rg = lane * 4;
    int cg = warp * 16;
    int blockRow = blockIdx.x * 128;

    unsigned long long acc[4][8];
    #pragma unroll
    for (int r = 0; r < 4; r++)
        #pragma unroll
        for (int p = 0; p < 8; p++) acc[r][p] = 0ULL;

    #pragma unroll
    for (int phase = 0; phase < 4; phase++) {
        int k0 = phase * KP;
        __syncthreads();
        #pragma unroll
        for (int i = 0; i < 4; i++) {
            int idx = i * 256 + t;
            int k = idx >> 5, cc = idx & 31;
            *(float4*)&sW[k][cc * 4] =
                __ldg((const float4*)(W + (size_t)(k0 + k) * 128) + cc);
        }
        #pragma unroll
        for (int i = 0; i < 4; i++) {
            int idx = i * 256 + t;
            int row = idx >> 3, k4 = idx & 7;
            int gr = blockRow + row;
            if (gr >= N_NODES) gr = N_NODES - 1;
            float4 v = __ldg((const float4*)(x + (size_t)gr * 128 + k0) + k4);
            sX[k4 * 4 + 0][row] = v.x;
            sX[k4 * 4 + 1][row] = v.y;
            sX[k4 * 4 + 2][row] = v.z;
            sX[k4 * 4 + 3][row] = v.w;
        }
        __syncthreads();

        #pragma unroll
        for (int k = 0; k < KP; k++) {
            float4 xv = *(const float4*)&sX[k][rg];
            const ulonglong2* wq = (const ulonglong2*)&sW[k][cg];
            ulonglong2 q0 = wq[0], q1 = wq[1], q2 = wq[2], q3 = wq[3];
            unsigned long long xb[4];
            xb[0] = bcast2(xv.x); xb[1] = bcast2(xv.y);
            xb[2] = bcast2(xv.z); xb[3] = bcast2(xv.w);
            #pragma unroll
            for (int r = 0; r < 4; r++) {
                ffma2(acc[r][0], xb[r], q0.x);
                ffma2(acc[r][1], xb[r], q0.y);
                ffma2(acc[r][2], xb[r], q1.x);
                ffma2(acc[r][3], xb[r], q1.y);
                ffma2(acc[r][4], xb[r], q2.x);
                ffma2(acc[r][5], xb[r], q2.y);
                ffma2(acc[r][6], xb[r], q3.x);
                ffma2(acc[r][7], xb[r], q3.y);
            }
        }
    }

    int h  = warp >> 1;
    int cb = cg & 31;
    const float* ai = att + h * 68 + cb;
    const float* aj = att + h * 68 + 32 + cb;

    #pragma unroll
    for (int r = 0; r < 4; r++) {
        int grow = blockRow + rg + r;
        __half2 hh[8];
        float psi = 0.0f, psj = 0.0f;
        #pragma unroll
        for (int p = 0; p < 8; p++) {
            float2 f = unpack2(acc[r][p]);
            hh[p] = __floats2half2_rn(f.x, f.y);
            float a0 = __ldg(ai + 2 * p), a1 = __ldg(ai + 2 * p + 1);
            float b0 = __ldg(aj + 2 * p), b1 = __ldg(aj + 2 * p + 1);
            psi += f.x * a0 + f.y * a1;
            psj += f.x * b0 + f.y * b1;
        }
        if (grow < N_NODES) {
            uint4 v0, v1;
            v0.x = *(unsigned*)&hh[0]; v0.y = *(unsigned*)&hh[1];
            v0.z = *(unsigned*)&hh[2]; v0.w = *(unsigned*)&hh[3];
            v1.x = *(unsigned*)&hh[4]; v1.y = *(unsigned*)&hh[5];
            v1.z = *(unsigned*)&hh[6]; v1.w = *(unsigned*)&hh[7];
            uint4* dst = (uint4*)(g_xh16 + (size_t)grow * 128 + cg);
            dst[0] = v0; dst[1] = v1;
        }
        sSi[warp][lane][r] = psi;
        sSj[warp][lane][r] = psj;
    }
    __syncthreads();

    #pragma unroll
    for (int ii = 0; ii < 2; ii++) {
        int idx = t + ii * 256;
        int h2 = idx >> 7, R = idx & 127;
        float si = sSi[2 * h2][R >> 2][R & 3] + sSi[2 * h2 + 1][R >> 2][R & 3];
        float sj = sSj[2 * h2][R >> 2][R & 3] + sSj[2 * h2 + 1][R >> 2][R & 3];
        int grow = blockRow + R;
        if (grow < N_NODES) {
            g_si[grow * 4 + h2] = si;
            g_sj[grow * 4 + h2] = sj;
        }
    }
}

// ---------------- K2: single-pass decoupled-lookback scan -------------------
__global__ __launch_bounds__(256) void k_scan() {
    __shared__ int sh[256];
    __shared__ int s_excl;
    int t = threadIdx.x, b = blockIdx.x;
    int i = b * 256 + t;
    int c = (i < N_NODES) ? g_cur[i] : 0;
    sh[t] = c;
    __syncthreads();
    int own = c;
    #pragma unroll
    for (int off = 1; off < 256; off <<= 1) {
        int v = (t >= off) ? sh[t - off] : 0;
        __syncthreads();
        sh[t] += v;
        __syncthreads();
    }
    int total = sh[255];

    if (t == 0) {
        if (b == 0) {
            s_excl = 0;
            atomicExch(&g_state[0], (2ULL << 62) | (unsigned)total);
        } else {
            atomicExch(&g_state[b], (1ULL << 62) | (unsigned)total);
            long long run = 0;
            int j = b - 1;
            while (true) {
                unsigned long long s;
                do { s = atomicAdd(&g_state[j], 0ULL); } while ((s >> 62) == 0ULL);
                run += (long long)(s & 0xffffffffULL);
                if ((s >> 62) == 2ULL) break;
                j--;
            }
            s_excl = (int)run;
            atomicExch(&g_state[b], (2ULL << 62) | (unsigned)(run + total));
        }
    }
    __syncthreads();
    int pre = s_excl;
    if (i < N_NODES) {
        int o = sh[t] - own + pre;
        g_off[i] = o;
        g_cur[i] = o;
    }
}

// ---------------- K3: edge logits -> exp(fp16), packed 16B scatter ----------
__global__ void k_edge(const int* __restrict__ ei, const float* __restrict__ eattr) {
    int e = blockIdx.x * blockDim.x + threadIdx.x;
    if (e >= N_EDGES) return;
    int src = __ldg(ei + e);
    int dst = __ldg(ei + N_EDGES + e);
    float4 f0 = __ldg((const float4*)eattr + (size_t)e * 2);
    float4 f1 = __ldg((const float4*)eattr + (size_t)e * 2 + 1);
    float f[8] = {f0.x, f0.y, f0.z, f0.w, f1.x, f1.y, f1.z, f1.w};
    float4 si = *(const float4*)(g_si + dst * 4);
    float4 sj = *(const float4*)(g_sj + src * 4);
    float sih[4] = {si.x, si.y, si.z, si.w};
    float sjh[4] = {sj.x, sj.y, sj.z, sj.w};
    float a[4];
    #pragma unroll
    for (int h = 0; h < 4; h++) {
        float se = 0.0f;
        #pragma unroll
        for (int c = 0; c < 8; c++) se += f[c] * g_sew[c * 4 + h];
        float v = sih[h] + sjh[h] + se;
        v = v > 0.0f ? v : NEG_SLOPE * v;
        a[h] = __expf(v);   // logits are O(1); exp without max shift is safe in fp32
    }
    __half2 h01 = __floats2half2_rn(a[0], a[1]);
    __half2 h23 = __floats2half2_rn(a[2], a[3]);
    int4 rec;
    rec.x = src;
    rec.y = *(int*)&h01;
    rec.z = *(int*)&h23;
    rec.w = 0;
    int pos = atomicAdd(&g_cur[dst], 1);
    g_rec[pos] = rec;
}

// ---------------- K4: warp-per-node aggregation (fp16 gather) ----------------
__global__ __launch_bounds__(256) void k_aggr(const float* __restrict__ bias,
                                              float* __restrict__ out) {
    int w = (blockIdx.x * blockDim.x + threadIdx.x) >> 5;
    if (w >= N_NODES) return;
    int lane = threadIdx.x & 31;
    int h = lane >> 3;

    int start = g_off[w];
    int end   = g_off[w + 1];

    float ax = 0.0f, ay = 0.0f, az = 0.0f, aw = 0.0f, den = 0.0f;

    #pragma unroll 4
    for (int e = start; e < end; e++) {
        int4 rec = __ldg(&g_rec[e]);
        int src = rec.x;
        float2 a01 = __half22float2(*(__half2*)&rec.y);
        float2 a23 = __half22float2(*(__half2*)&rec.z);
        float ea = (h == 0) ? a01.x : (h == 1) ? a01.y : (h == 2) ? a23.x : a23.y;
        den += ea;
        uint2 u = __ldg((const uint2*)(g_xh16 + (size_t)src * 128) + lane);
        float2 f0 = __half22float2(*(__half2*)&u.x);
        float2 f1 = __half22float2(*(__half2*)&u.y);
        ax += ea * f0.x; ay += ea * f0.y; az += ea * f1.x; aw += ea * f1.y;
    }

    float inv = 1.0f / (den + 1e-16f);
    float4 b = __ldg((const float4*)bias + lane);
    ((float4*)out)[(size_t)w * 32 + lane] =
        make_float4(ax * inv + b.x, ay * inv + b.y, az * inv + b.z, aw * inv + b.w);
}

// ---------------- launch ----------------------------------------------------
extern "C" void kernel_launch(void* const* d_in, const int* in_sizes, int n_in,
                              void* d_out, int out_size) {
    const float* x     = (const float*)d_in[0];
    const int*   ei    = (const int*)  d_in[1];
    const float* eattr = (const float*)d_in[2];
    const float* W     = (const float*)d_in[3];
    const float* We    = (const float*)d_in[4];
    const float* att   = (const float*)d_in[5];
    const float* bias  = (const float*)d_in[6];
    float* out = (float*)d_out;

    k_init     <<<(N_NODES + 255) / 256, 256>>>(We, att);
    k_gemm_hist<<<GEMM_B + HIST_B, 256>>>(x, W, att, ei);
    k_scan     <<<SCAN_B, 256>>>();
    k_edge     <<<(N_EDGES + 255) / 256, 256>>>(ei, eattr);
    k_aggr     <<<((size_t)N_NODES * 32 + 255) / 256, 256>>>(bias, out);
}

// round 15
// speedup vs baseline: 1.0887x; 1.0887x over previous
#include <cuda_runtime.h>
#include <cuda_fp16.h>

#define N_NODES 50000
#define N_EDGES 800000
#define NEG_SLOPE 0.2f
#define SCAN_B 196          // ceil(50000/256)
#define GEMM_B 391          // ceil(50000/128)
#define HIST_B 196

// ---------------- scratch (device globals) ---------------------------------
__device__ __align__(16) __half g_xh16[(size_t)N_NODES * 128]; // x @ W in fp16
__device__ __align__(16) float g_si[N_NODES * 4];
__device__ __align__(16) float g_sj[N_NODES * 4];
__device__ float g_sew[32];                                 // folded We * a_e  [c][h]
__device__ int   g_cur[N_NODES];                            // counts -> cursors
__device__ int   g_off[N_NODES + 1];                        // CSR offsets by dst
__device__ unsigned long long g_state[SCAN_B];              // lookback scan state
__device__ int   g_ssrc[N_EDGES];                           // dst-sorted src ids
__device__ __align__(16) float g_salpha[(size_t)N_EDGES * 4]; // dst-sorted exp(logit)

// ---------------- f32x2 packed-FMA helpers (Blackwell FFMA2) ----------------
__device__ __forceinline__ void ffma2(unsigned long long& d,
                                      unsigned long long a,
                                      unsigned long long b) {
    asm("fma.rn.f32x2 %0, %1, %2, %0;" : "+l"(d) : "l"(a), "l"(b));
}
__device__ __forceinline__ unsigned long long bcast2(float x) {
    unsigned long long r;
    unsigned int u = __float_as_uint(x);
    asm("mov.b64 %0, {%1, %1};" : "=l"(r) : "r"(u));
    return r;
}
__device__ __forceinline__ float2 unpack2(unsigned long long v) {
    unsigned int a, b;
    asm("mov.b64 {%0, %1}, %2;" : "=r"(a), "=r"(b) : "l"(v));
    return make_float2(__uint_as_float(a), __uint_as_float(b));
}

// ---------------- K0: init counts, scan state, fold We*a_e ------------------
__global__ void k_init(const float* __restrict__ We, const float* __restrict__ att) {
    int i = blockIdx.x * blockDim.x + threadIdx.x;
    if (i < N_NODES) g_cur[i] = 0;
    if (i < SCAN_B) g_state[i] = 0ULL;
    if (i == 0) g_off[N_NODES] = N_EDGES;
    if (i < 32) {
        int h = i & 3, c = i >> 2;
        float s = 0.0f;
        #pragma unroll
        for (int p = 0; p < 4; p++)
            s += __ldg(We + c * 16 + h * 4 + p) * __ldg(att + h * 68 + 64 + p);
        g_sew[c * 4 + h] = s;
    }
}

// ---------------- K1: heterogeneous grid: GEMM tiles + dst histogram --------
#define KP 32
#define XSTR 132
__global__ __launch_bounds__(256, 2) void k_gemm_hist(const float* __restrict__ x,
                                                      const float* __restrict__ W,
                                                      const float* __restrict__ att,
                                                      const int* __restrict__ ei) {
    __shared__ __align__(16) float sW[KP][128];
    __shared__ __align__(16) float sX[KP][XSTR];
    __shared__ float sSi[8][32][4];
    __shared__ float sSj[8][32][4];
    int t = threadIdx.x;

    if (blockIdx.x >= GEMM_B) {
        int base = (blockIdx.x - GEMM_B) * 256 + t;
        const int stride = HIST_B * 256;
        #pragma unroll 4
        for (int e = base; e < N_EDGES; e += stride)
            atomicAdd(&g_cur[__ldg(ei + N_EDGES + e)], 1);
        return;
    }

    int lane = t & 31;
    int warp = t >> 5;
    int rg = lane * 4;
    int cg = warp * 16;
    int blockRow = blockIdx.x * 128;

    unsigned long long acc[4][8];
    #pragma unroll
    for (int r = 0; r < 4; r++)
        #pragma unroll
        for (int p = 0; p < 8; p++) acc[r][p] = 0ULL;

    #pragma unroll
    for (int phase = 0; phase < 4; phase++) {
        int k0 = phase * KP;
        __syncthreads();
        #pragma unroll
        for (int i = 0; i < 4; i++) {
            int idx = i * 256 + t;
            int k = idx >> 5, cc = idx & 31;
            *(float4*)&sW[k][cc * 4] =
                __ldg((const float4*)(W + (size_t)(k0 + k) * 128) + cc);
        }
        #pragma unroll
        for (int i = 0; i < 4; i++) {
            int idx = i * 256 + t;
            int row = idx >> 3, k4 = idx & 7;
            int gr = blockRow + row;
            if (gr >= N_NODES) gr = N_NODES - 1;
            float4 v = __ldg((const float4*)(x + (size_t)gr * 128 + k0) + k4);
            sX[k4 * 4 + 0][row] = v.x;
            sX[k4 * 4 + 1][row] = v.y;
            sX[k4 * 4 + 2][row] = v.z;
            sX[k4 * 4 + 3][row] = v.w;
        }
        __syncthreads();

        #pragma unroll
        for (int k = 0; k < KP; k++) {
            float4 xv = *(const float4*)&sX[k][rg];
            const ulonglong2* wq = (const ulonglong2*)&sW[k][cg];
            ulonglong2 q0 = wq[0], q1 = wq[1], q2 = wq[2], q3 = wq[3];
            unsigned long long xb[4];
            xb[0] = bcast2(xv.x); xb[1] = bcast2(xv.y);
            xb[2] = bcast2(xv.z); xb[3] = bcast2(xv.w);
            #pragma unroll
            for (int r = 0; r < 4; r++) {
                ffma2(acc[r][0], xb[r], q0.x);
                ffma2(acc[r][1], xb[r], q0.y);
                ffma2(acc[r][2], xb[r], q1.x);
                ffma2(acc[r][3], xb[r], q1.y);
                ffma2(acc[r][4], xb[r], q2.x);
                ffma2(acc[r][5], xb[r], q2.y);
                ffma2(acc[r][6], xb[r], q3.x);
                ffma2(acc[r][7], xb[r], q3.y);
            }
        }
    }

    int h  = warp >> 1;
    int cb = cg & 31;
    const float* ai = att + h * 68 + cb;
    const float* aj = att + h * 68 + 32 + cb;

    #pragma unroll
    for (int r = 0; r < 4; r++) {
        int grow = blockRow + rg + r;
        __half2 hh[8];
        float psi = 0.0f, psj = 0.0f;
        #pragma unroll
        for (int p = 0; p < 8; p++) {
            float2 f = unpack2(acc[r][p]);
            hh[p] = __floats2half2_rn(f.x, f.y);
            float a0 = __ldg(ai + 2 * p), a1 = __ldg(ai + 2 * p + 1);
            float b0 = __ldg(aj + 2 * p), b1 = __ldg(aj + 2 * p + 1);
            psi += f.x * a0 + f.y * a1;
            psj += f.x * b0 + f.y * b1;
        }
        if (grow < N_NODES) {
            uint4 v0, v1;
            v0.x = *(unsigned*)&hh[0]; v0.y = *(unsigned*)&hh[1];
            v0.z = *(unsigned*)&hh[2]; v0.w = *(unsigned*)&hh[3];
            v1.x = *(unsigned*)&hh[4]; v1.y = *(unsigned*)&hh[5];
            v1.z = *(unsigned*)&hh[6]; v1.w = *(unsigned*)&hh[7];
            uint4* dst = (uint4*)(g_xh16 + (size_t)grow * 128 + cg);
            dst[0] = v0; dst[1] = v1;
        }
        sSi[warp][lane][r] = psi;
        sSj[warp][lane][r] = psj;
    }
    __syncthreads();

    #pragma unroll
    for (int ii = 0; ii < 2; ii++) {
        int idx = t + ii * 256;
        int h2 = idx >> 7, R = idx & 127;
        float si = sSi[2 * h2][R >> 2][R & 3] + sSi[2 * h2 + 1][R >> 2][R & 3];
        float sj = sSj[2 * h2][R >> 2][R & 3] + sSj[2 * h2 + 1][R >> 2][R & 3];
        int grow = blockRow + R;
        if (grow < N_NODES) {
            g_si[grow * 4 + h2] = si;
            g_sj[grow * 4 + h2] = sj;
        }
    }
}

// ---------------- K2: single-pass decoupled-lookback scan -------------------
__global__ __launch_bounds__(256) void k_scan() {
    __shared__ int sh[256];
    __shared__ int s_excl;
    int t = threadIdx.x, b = blockIdx.x;
    int i = b * 256 + t;
    int c = (i < N_NODES) ? g_cur[i] : 0;
    sh[t] = c;
    __syncthreads();
    int own = c;
    #pragma unroll
    for (int off = 1; off < 256; off <<= 1) {
        int v = (t >= off) ? sh[t - off] : 0;
        __syncthreads();
        sh[t] += v;
        __syncthreads();
    }
    int total = sh[255];

    if (t == 0) {
        if (b == 0) {
            s_excl = 0;
            atomicExch(&g_state[0], (2ULL << 62) | (unsigned)total);
        } else {
            atomicExch(&g_state[b], (1ULL << 62) | (unsigned)total);
            long long run = 0;
            int j = b - 1;
            while (true) {
                unsigned long long s;
                do { s = atomicAdd(&g_state[j], 0ULL); } while ((s >> 62) == 0ULL);
                run += (long long)(s & 0xffffffffULL);
                if ((s >> 62) == 2ULL) break;
                j--;
            }
            s_excl = (int)run;
            atomicExch(&g_state[b], (2ULL << 62) | (unsigned)(run + total));
        }
    }
    __syncthreads();
    int pre = s_excl;
    if (i < N_NODES) {
        int o = sh[t] - own + pre;
        g_off[i] = o;
        g_cur[i] = o;
    }
}

// ---------------- K3: edge logits -> exp, scatter into CSR ------------------
__global__ void k_edge(const int* __restrict__ ei, const float* __restrict__ eattr) {
    int e = blockIdx.x * blockDim.x + threadIdx.x;
    if (e >= N_EDGES) return;
    int src = __ldg(ei + e);
    int dst = __ldg(ei + N_EDGES + e);
    float4 f0 = __ldg((const float4*)eattr + (size_t)e * 2);
    float4 f1 = __ldg((const float4*)eattr + (size_t)e * 2 + 1);
    float f[8] = {f0.x, f0.y, f0.z, f0.w, f1.x, f1.y, f1.z, f1.w};
    float4 si = *(const float4*)(g_si + dst * 4);
    float4 sj = *(const float4*)(g_sj + src * 4);
    float sih[4] = {si.x, si.y, si.z, si.w};
    float sjh[4] = {sj.x, sj.y, sj.z, sj.w};
    float a[4];
    #pragma unroll
    for (int h = 0; h < 4; h++) {
        float se = 0.0f;
        #pragma unroll
        for (int c = 0; c < 8; c++) se += f[c] * g_sew[c * 4 + h];
        float v = sih[h] + sjh[h] + se;
        v = v > 0.0f ? v : NEG_SLOPE * v;
        a[h] = __expf(v);   // logits are O(1); exp without max shift is safe in fp32
    }
    int pos = atomicAdd(&g_cur[dst], 1);
    g_ssrc[pos] = src;
    *((float4*)g_salpha + pos) = make_float4(a[0], a[1], a[2], a[3]);
}

// ---------------- K4: warp-per-node aggregation (prefetch-pipelined) --------
__global__ __launch_bounds__(256) void k_aggr(const float* __restrict__ bias,
                                              float* __restrict__ out) {
    int w = (blockIdx.x * blockDim.x + threadIdx.x) >> 5;
    if (w >= N_NODES) return;
    int lane = threadIdx.x & 31;
    int h = lane >> 3;

    int start = g_off[w];
    int end   = g_off[w + 1];

    float ax = 0.0f, ay = 0.0f, az = 0.0f, aw = 0.0f, den = 0.0f;

    if (start < end) {
        // stage 0 prefetch
        int   srcN = __ldg(&g_ssrc[start]);
        float eaN  = __ldg(&g_salpha[(size_t)start * 4 + h]);
        uint2 uN   = __ldg((const uint2*)(g_xh16 + (size_t)srcN * 128) + lane);

        for (int e = start; e < end; e++) {
            float ea = eaN;
            uint2 u  = uN;
            if (e + 1 < end) {
                // issue next edge's loads before consuming current (hides L2 latency)
                int srcn = __ldg(&g_ssrc[e + 1]);
                eaN = __ldg(&g_salpha[(size_t)(e + 1) * 4 + h]);
                uN  = __ldg((const uint2*)(g_xh16 + (size_t)srcn * 128) + lane);
            }
            den += ea;
            float2 f0 = __half22float2(*(__half2*)&u.x);
            float2 f1 = __half22float2(*(__half2*)&u.y);
            ax += ea * f0.x; ay += ea * f0.y; az += ea * f1.x; aw += ea * f1.y;
        }
    }

    float inv = 1.0f / (den + 1e-16f);
    float4 b = __ldg((const float4*)bias + lane);
    ((float4*)out)[(size_t)w * 32 + lane] =
        make_float4(ax * inv + b.x, ay * inv + b.y, az * inv + b.z, aw * inv + b.w);
}

// ---------------- launch ----------------------------------------------------
extern "C" void kernel_launch(void* const* d_in, const int* in_sizes, int n_in,
                              void* d_out, int out_size) {
    const float* x     = (const float*)d_in[0];
    const int*   ei    = (const int*)  d_in[1];
    const float* eattr = (const float*)d_in[2];
    const float* W     = (const float*)d_in[3];
    const float* We    = (const float*)d_in[4];
    const float* att   = (const float*)d_in[5];
    const float* bias  = (const float*)d_in[6];
    float* out = (float*)d_out;

    k_init     <<<(N_NODES + 255) / 256, 256>>>(We, att);
    k_gemm_hist<<<GEMM_B + HIST_B, 256>>>(x, W, att, ei);
    k_scan     <<<SCAN_B, 256>>>();
    k_edge     <<<(N_EDGES + 255) / 256, 256>>>(ei, eattr);
    k_aggr     <<<((size_t)N_NODES * 32 + 255) / 256, 256>>>(bias, out);
}

// round 16
// speedup vs baseline: 1.1529x; 1.0590x over previous
#include <cuda_runtime.h>
#include <cuda_fp16.h>

#define N_NODES 50000
#define N_EDGES 800000
#define NEG_SLOPE 0.2f
#define SCAN_B 196          // ceil(50000/256)
#define GEMM_B 391          // ceil(50000/128)
#define HIST_B 196

// ---------------- scratch (device globals) ---------------------------------
__device__ __align__(16) __half g_xh16[(size_t)N_NODES * 128]; // x @ W in fp16
__device__ __align__(16) float g_si[N_NODES * 4];
__device__ __align__(16) float g_sj[N_NODES * 4];
__device__ float g_sew[32];                                 // folded We * a_e  [c][h]
__device__ int   g_cur[N_NODES];                            // counts -> cursors
__device__ int   g_off[N_NODES + 1];                        // CSR offsets by dst
__device__ unsigned long long g_state[SCAN_B];              // lookback scan state
__device__ int   g_ssrc[N_EDGES];                           // dst-sorted src ids
__device__ __align__(16) float g_salpha[(size_t)N_EDGES * 4]; // dst-sorted sj[src]+se per head

// ---------------- f32x2 packed-FMA helpers (Blackwell FFMA2) ----------------
__device__ __forceinline__ void ffma2(unsigned long long& d,
                                      unsigned long long a,
                                      unsigned long long b) {
    asm("fma.rn.f32x2 %0, %1, %2, %0;" : "+l"(d) : "l"(a), "l"(b));
}
__device__ __forceinline__ unsigned long long bcast2(float x) {
    unsigned long long r;
    unsigned int u = __float_as_uint(x);
    asm("mov.b64 %0, {%1, %1};" : "=l"(r) : "r"(u));
    return r;
}
__device__ __forceinline__ float2 unpack2(unsigned long long v) {
    unsigned int a, b;
    asm("mov.b64 {%0, %1}, %2;" : "=r"(a), "=r"(b) : "l"(v));
    return make_float2(__uint_as_float(a), __uint_as_float(b));
}

// ---------------- K0: init counts, scan state, fold We*a_e ------------------
__global__ void k_init(const float* __restrict__ We, const float* __restrict__ att) {
    int i = blockIdx.x * blockDim.x + threadIdx.x;
    if (i < N_NODES) g_cur[i] = 0;
    if (i < SCAN_B) g_state[i] = 0ULL;
    if (i == 0) g_off[N_NODES] = N_EDGES;
    if (i < 32) {
        int h = i & 3, c = i >> 2;
        float s = 0.0f;
        #pragma unroll
        for (int p = 0; p < 4; p++)
            s += __ldg(We + c * 16 + h * 4 + p) * __ldg(att + h * 68 + 64 + p);
        g_sew[c * 4 + h] = s;
    }
}

// ---------------- K1: heterogeneous grid: GEMM tiles + dst histogram --------
#define KP 32
#define XSTR 132
__global__ __launch_bounds__(256, 2) void k_gemm_hist(const float* __restrict__ x,
                                                      const float* __restrict__ W,
                                                      const float* __restrict__ att,
                                                      const int* __restrict__ ei) {
    __shared__ __align__(16) float sW[KP][128];
    __shared__ __align__(16) float sX[KP][XSTR];
    __shared__ float sSi[8][32][4];
    __shared__ float sSj[8][32][4];
    int t = threadIdx.x;

    if (blockIdx.x >= GEMM_B) {
        int base = (blockIdx.x - GEMM_B) * 256 + t;
        const int stride = HIST_B * 256;
        #pragma unroll 4
        for (int e = base; e < N_EDGES; e += stride)
            atomicAdd(&g_cur[__ldg(ei + N_EDGES + e)], 1);
        return;
    }

    int lane = t & 31;
    int warp = t >> 5;
    int rg = lane * 4;
    int cg = warp * 16;
    int blockRow = blockIdx.x * 128;

    unsigned long long acc[4][8];
    #pragma unroll
    for (int r = 0; r < 4; r++)
        #pragma unroll
        for (int p = 0; p < 8; p++) acc[r][p] = 0ULL;

    #pragma unroll
    for (int phase = 0; phase < 4; phase++) {
        int k0 = phase * KP;
        __syncthreads();
        #pragma unroll
        for (int i = 0; i < 4; i++) {
            int idx = i * 256 + t;
            int k = idx >> 5, cc = idx & 31;
            *(float4*)&sW[k][cc * 4] =
                __ldg((const float4*)(W + (size_t)(k0 + k) * 128) + cc);
        }
        #pragma unroll
        for (int i = 0; i < 4; i++) {
            int idx = i * 256 + t;
            int row = idx >> 3, k4 = idx & 7;
            int gr = blockRow + row;
            if (gr >= N_NODES) gr = N_NODES - 1;
            float4 v = __ldg((const float4*)(x + (size_t)gr * 128 + k0) + k4);
            sX[k4 * 4 + 0][row] = v.x;
            sX[k4 * 4 + 1][row] = v.y;
            sX[k4 * 4 + 2][row] = v.z;
            sX[k4 * 4 + 3][row] = v.w;
        }
        __syncthreads();

        #pragma unroll
        for (int k = 0; k < KP; k++) {
            float4 xv = *(const float4*)&sX[k][rg];
            const ulonglong2* wq = (const ulonglong2*)&sW[k][cg];
            ulonglong2 q0 = wq[0], q1 = wq[1], q2 = wq[2], q3 = wq[3];
            unsigned long long xb[4];
            xb[0] = bcast2(xv.x); xb[1] = bcast2(xv.y);
            xb[2] = bcast2(xv.z); xb[3] = bcast2(xv.w);
            #pragma unroll
            for (int r = 0; r < 4; r++) {
                ffma2(acc[r][0], xb[r], q0.x);
                ffma2(acc[r][1], xb[r], q0.y);
                ffma2(acc[r][2], xb[r], q1.x);
                ffma2(acc[r][3], xb[r], q1.y);
                ffma2(acc[r][4], xb[r], q2.x);
                ffma2(acc[r][5], xb[r], q2.y);
                ffma2(acc[r][6], xb[r], q3.x);
                ffma2(acc[r][7], xb[r], q3.y);
            }
        }
    }

    int h  = warp >> 1;
    int cb = cg & 31;
    const float* ai = att + h * 68 + cb;
    const float* aj = att + h * 68 + 32 + cb;

    #pragma unroll
    for (int r = 0; r < 4; r++) {
        int grow = blockRow + rg + r;
        __half2 hh[8];
        float psi = 0.0f, psj = 0.0f;
        #pragma unroll
        for (int p = 0; p < 8; p++) {
            float2 f = unpack2(acc[r][p]);
            hh[p] = __floats2half2_rn(f.x, f.y);
            float a0 = __ldg(ai + 2 * p), a1 = __ldg(ai + 2 * p + 1);
            float b0 = __ldg(aj + 2 * p), b1 = __ldg(aj + 2 * p + 1);
            psi += f.x * a0 + f.y * a1;
            psj += f.x * b0 + f.y * b1;
        }
        if (grow < N_NODES) {
            uint4 v0, v1;
            v0.x = *(unsigned*)&hh[0]; v0.y = *(unsigned*)&hh[1];
            v0.z = *(unsigned*)&hh[2]; v0.w = *(unsigned*)&hh[3];
            v1.x = *(unsigned*)&hh[4]; v1.y = *(unsigned*)&hh[5];
            v1.z = *(unsigned*)&hh[6]; v1.w = *(unsigned*)&hh[7];
            uint4* dst = (uint4*)(g_xh16 + (size_t)grow * 128 + cg);
            dst[0] = v0; dst[1] = v1;
        }
        sSi[warp][lane][r] = psi;
        sSj[warp][lane][r] = psj;
    }
    __syncthreads();

    #pragma unroll
    for (int ii = 0; ii < 2; ii++) {
        int idx = t + ii * 256;
        int h2 = idx >> 7, R = idx & 127;
        float si = sSi[2 * h2][R >> 2][R & 3] + sSi[2 * h2 + 1][R >> 2][R & 3];
        float sj = sSj[2 * h2][R >> 2][R & 3] + sSj[2 * h2 + 1][R >> 2][R & 3];
        int grow = blockRow + R;
        if (grow < N_NODES) {
            g_si[grow * 4 + h2] = si;
            g_sj[grow * 4 + h2] = sj;
        }
    }
}

// ---------------- K2: single-pass decoupled-lookback scan -------------------
__global__ __launch_bounds__(256) void k_scan() {
    __shared__ int sh[256];
    __shared__ int s_excl;
    int t = threadIdx.x, b = blockIdx.x;
    int i = b * 256 + t;
    int c = (i < N_NODES) ? g_cur[i] : 0;
    sh[t] = c;
    __syncthreads();
    int own = c;
    #pragma unroll
    for (int off = 1; off < 256; off <<= 1) {
        int v = (t >= off) ? sh[t - off] : 0;
        __syncthreads();
        sh[t] += v;
        __syncthreads();
    }
    int total = sh[255];

    if (t == 0) {
        if (b == 0) {
            s_excl = 0;
            atomicExch(&g_state[0], (2ULL << 62) | (unsigned)total);
        } else {
            atomicExch(&g_state[b], (1ULL << 62) | (unsigned)total);
            long long run = 0;
            int j = b - 1;
            while (true) {
                unsigned long long s;
                do { s = atomicAdd(&g_state[j], 0ULL); } while ((s >> 62) == 0ULL);
                run += (long long)(s & 0xffffffffULL);
                if ((s >> 62) == 2ULL) break;
                j--;
            }
            s_excl = (int)run;
            atomicExch(&g_state[b], (2ULL << 62) | (unsigned)(run + total));
        }
    }
    __syncthreads();
    int pre = s_excl;
    if (i < N_NODES) {
        int o = sh[t] - own + pre;
        g_off[i] = o;
        g_cur[i] = o;
    }
}

// ---------------- K3: edge partial logits t = sj[src]+se, scatter into CSR --
// (si[dst], leakyrelu and exp are applied in k_aggr — saves the si gather here)
__global__ void k_edge(const int* __restrict__ ei, const float* __restrict__ eattr) {
    int e = blockIdx.x * blockDim.x + threadIdx.x;
    if (e >= N_EDGES) return;
    int src = __ldg(ei + e);
    int dst = __ldg(ei + N_EDGES + e);
    float4 f0 = __ldg((const float4*)eattr + (size_t)e * 2);
    float4 f1 = __ldg((const float4*)eattr + (size_t)e * 2 + 1);
    float f[8] = {f0.x, f0.y, f0.z, f0.w, f1.x, f1.y, f1.z, f1.w};
    float4 sj = *(const float4*)(g_sj + src * 4);
    float sjh[4] = {sj.x, sj.y, sj.z, sj.w};
    float a[4];
    #pragma unroll
    for (int h = 0; h < 4; h++) {
        float se = 0.0f;
        #pragma unroll
        for (int c = 0; c < 8; c++) se += f[c] * g_sew[c * 4 + h];
        a[h] = sjh[h] + se;
    }
    int pos = atomicAdd(&g_cur[dst], 1);
    g_ssrc[pos] = src;
    *((float4*)g_salpha + pos) = make_float4(a[0], a[1], a[2], a[3]);
}

// ---------------- K4: warp-per-node aggregation (R13 loop + fused softmax) --
__global__ __launch_bounds__(256) void k_aggr(const float* __restrict__ bias,
                                              float* __restrict__ out) {
    int w = (blockIdx.x * blockDim.x + threadIdx.x) >> 5;
    if (w >= N_NODES) return;
    int lane = threadIdx.x & 31;
    int h = lane >> 3;

    int start = g_off[w];
    int end   = g_off[w + 1];

    float si_h = __ldg(&g_si[w * 4 + h]);   // per-node broadcast (8 lanes/head share)

    float ax = 0.0f, ay = 0.0f, az = 0.0f, aw = 0.0f, den = 0.0f;

    #pragma unroll 4
    for (int e = start; e < end; e++) {
        int src = __ldg(&g_ssrc[e]);
        float tv = __ldg(&g_salpha[(size_t)e * 4 + h]);
        float v = si_h + tv;
        v = v > 0.0f ? v : NEG_SLOPE * v;
        float ea = __expf(v);
        den += ea;
        uint2 u = __ldg((const uint2*)(g_xh16 + (size_t)src * 128) + lane);
        float2 f0 = __half22float2(*(__half2*)&u.x);
        float2 f1 = __half22float2(*(__half2*)&u.y);
        ax += ea * f0.x; ay += ea * f0.y; az += ea * f1.x; aw += ea * f1.y;
    }

    float inv = 1.0f / (den + 1e-16f);
    float4 b = __ldg((const float4*)bias + lane);
    ((float4*)out)[(size_t)w * 32 + lane] =
        make_float4(ax * inv + b.x, ay * inv + b.y, az * inv + b.z, aw * inv + b.w);
}

// ---------------- launch ----------------------------------------------------
extern "C" void kernel_launch(void* const* d_in, const int* in_sizes, int n_in,
                              void* d_out, int out_size) {
    const float* x     = (const float*)d_in[0];
    const int*   ei    = (const int*)  d_in[1];
    const float* eattr = (const float*)d_in[2];
    const float* W     = (const float*)d_in[3];
    const float* We    = (const float*)d_in[4];
    const float* att   = (const float*)d_in[5];
    const float* bias  = (const float*)d_in[6];
    float* out = (float*)d_out;

    k_init     <<<(N_NODES + 255) / 256, 256>>>(We, att);
    k_gemm_hist<<<GEMM_B + HIST_B, 256>>>(x, W, att, ei);
    k_scan     <<<SCAN_B, 256>>>();
    k_edge     <<<(N_EDGES + 255) / 256, 256>>>(ei, eattr);
    k_aggr     <<<((size_t)N_NODES * 32 + 255) / 256, 256>>>(bias, out);
}